// round 10
// baseline (speedup 1.0000x reference)
#include <cuda_runtime.h>
#include <cuda_bf16.h>

// Problem constants (fixed shapes for this problem)
#define NN 50000
#define EE 800000
#define DD 128
#define HH 32

// -------- scratch (no allocations allowed) --------
__device__ __align__(16) float g_y1[NN * HH];    // x @ W1_l^T
__device__ __align__(16) float g_z1[NN * HH];    // x @ W1_r^T
__device__ __align__(16) float g_sl[NN];         // h @ W2_l^T
__device__ __align__(16) float g_sr[NN];         // h @ W2_r^T
__device__ int g_cnt[NN];                        // per-dst edge count
__device__ int g_rowptr[NN + 1];                 // CSR row pointers
__device__ int g_cur[NN];                        // reorder cursors
__device__ int g_esrc[EE];                       // CSR-ordered src indices
__device__ int g_bsum[256];                      // scan: per-block sums
__device__ int g_boff[256];                      // scan: per-block offsets
__device__ int g_is64;                           // edge_index dtype flag

// load node index (always < 2^31) as 32-bit regardless of storage width
__device__ __forceinline__ int edge_at32(const void* ei, long long pos, int is64) {
    return is64 ? ((const int*)ei)[2 * pos] : ((const int*)ei)[pos];
}

// -------- init: detect dtype (block 0) + zero counts --------
__global__ void init_kernel(const unsigned* __restrict__ ei_words, int n) {
    if (blockIdx.x == 0) {
        __shared__ int flag;
        if (threadIdx.x == 0) flag = 1;
        __syncthreads();
        unsigned w = ei_words[2 * threadIdx.x + 1];  // high words if int64
        if (w != 0u) flag = 0;
        __syncthreads();
        if (threadIdx.x == 0) g_is64 = flag;
    }
    for (int i = blockIdx.x * blockDim.x + threadIdx.x; i < n;
         i += gridDim.x * blockDim.x)
        g_cnt[i] = 0;
}

// -------- histogram of dst (2 edges/thread, strided for coalescing) --------
__global__ __launch_bounds__(256) void hist_kernel(const void* __restrict__ ei, long long E) {
    long long t = (long long)blockIdx.x * blockDim.x + threadIdx.x;
    long long Q = (E + 1) >> 1;
    if (t >= Q) return;
    int is64 = g_is64;
    int d0 = edge_at32(ei, E + t, is64);
    atomicAdd(&g_cnt[d0], 1);
    if (t + Q < E) {
        int d1 = edge_at32(ei, E + t + Q, is64);
        atomicAdd(&g_cnt[d1], 1);
    }
}

// -------- scan stage A: per-block sums of 256 counts --------
__global__ __launch_bounds__(256) void scanA_kernel(int n) {
    int tid = threadIdx.x;
    int i = blockIdx.x * 256 + tid;
    int c = (i < n) ? g_cnt[i] : 0;
    // block reduce
    int v = c;
#pragma unroll
    for (int o = 16; o; o >>= 1) v += __shfl_xor_sync(0xFFFFFFFFu, v, o);
    __shared__ int ws[8];
    if ((tid & 31) == 0) ws[tid >> 5] = v;
    __syncthreads();
    if (tid == 0) {
        int s = 0;
#pragma unroll
        for (int w = 0; w < 8; w++) s += ws[w];
        g_bsum[blockIdx.x] = s;
    }
}

// -------- scan stage B: exclusive scan of block sums (1 block) --------
__global__ __launch_bounds__(256) void scanB_kernel(int nb, int n, int Etot) {
    int tid = threadIdx.x;
    int lane = tid & 31, wid = tid >> 5;
    int c = (tid < nb) ? g_bsum[tid] : 0;
    int v = c;
#pragma unroll
    for (int o = 1; o < 32; o <<= 1) {
        int t = __shfl_up_sync(0xFFFFFFFFu, v, o);
        if (lane >= o) v += t;
    }
    __shared__ int ws[8];
    if (lane == 31) ws[wid] = v;
    __syncthreads();
    if (wid == 0 && lane < 8) {
        int w = ws[lane];
#pragma unroll
        for (int o = 1; o < 8; o <<= 1) {
            int t = __shfl_up_sync(0x000000FFu, w, o);
            if (lane >= o) w += t;
        }
        ws[lane] = w;
    }
    __syncthreads();
    int excl = v - c + (wid > 0 ? ws[wid - 1] : 0);
    if (tid < nb) g_boff[tid] = excl;
    if (tid == 0) g_rowptr[n] = Etot;
}

// -------- scan stage C: per-block exclusive scan + offset -> rowptr, cur --------
__global__ __launch_bounds__(256) void scanC_kernel(int n) {
    int tid = threadIdx.x;
    int lane = tid & 31, wid = tid >> 5;
    int i = blockIdx.x * 256 + tid;
    int c = (i < n) ? g_cnt[i] : 0;
    int v = c;
#pragma unroll
    for (int o = 1; o < 32; o <<= 1) {
        int t = __shfl_up_sync(0xFFFFFFFFu, v, o);
        if (lane >= o) v += t;
    }
    __shared__ int ws[8];
    if (lane == 31) ws[wid] = v;
    __syncthreads();
    if (wid == 0 && lane < 8) {
        int w = ws[lane];
#pragma unroll
        for (int o = 1; o < 8; o <<= 1) {
            int t = __shfl_up_sync(0x000000FFu, w, o);
            if (lane >= o) w += t;
        }
        ws[lane] = w;
    }
    __syncthreads();
    int excl = v - c + (wid > 0 ? ws[wid - 1] : 0) + g_boff[blockIdx.x];
    if (i < n) {
        g_rowptr[i] = excl;
        g_cur[i] = excl;
    }
}

// -------- reorder: build CSR-ordered src array, 4 edges/thread (ILP) --------
__global__ __launch_bounds__(256) void reorder_kernel(const void* __restrict__ ei, long long E) {
    long long t = (long long)blockIdx.x * blockDim.x + threadIdx.x;
    long long Q = (E + 3) >> 2;
    if (t >= Q) return;
    int is64 = g_is64;
    int src[4], dst[4];
    bool ok[4];
#pragma unroll
    for (int k = 0; k < 4; k++) {
        long long e = t + k * Q;
        ok[k] = (e < E);
        if (ok[k]) {
            src[k] = edge_at32(ei, e, is64);
            dst[k] = edge_at32(ei, E + e, is64);
        }
    }
    int pos[4];
#pragma unroll
    for (int k = 0; k < 4; k++)
        if (ok[k]) pos[k] = atomicAdd(&g_cur[dst[k]], 1);
#pragma unroll
    for (int k = 0; k < 4; k++)
        if (ok[k]) g_esrc[pos[k]] = src[k];
}

// -------- tf32 helpers --------
__device__ __forceinline__ unsigned f2tf32(float f) {
    unsigned u;
    asm("cvt.rna.tf32.f32 %0, %1;" : "=r"(u) : "f"(f));
    return u;
}
__device__ __forceinline__ void split_tf32(float f, unsigned& hi, unsigned& lo) {
    hi = f2tf32(f);
    float rem = f - __uint_as_float(hi);
    lo = f2tf32(rem);
}
__device__ __forceinline__ void mma_tf32(float* d, unsigned a0, unsigned a1,
                                         unsigned a2, unsigned a3,
                                         unsigned b0, unsigned b1) {
    asm volatile(
        "mma.sync.aligned.m16n8k8.row.col.f32.tf32.tf32.f32 "
        "{%0,%1,%2,%3}, {%4,%5,%6,%7}, {%8,%9}, {%0,%1,%2,%3};\n"
        : "+f"(d[0]), "+f"(d[1]), "+f"(d[2]), "+f"(d[3])
        : "r"(a0), "r"(a1), "r"(a2), "r"(a3), "r"(b0), "r"(b1));
}

// Dynamic smem layout: xs[64][132] then wt[128][72]
#define XS_STRIDE 132
#define WT_STRIDE 72
#define XS_ELEMS  (64 * XS_STRIDE)
#define WT_ELEMS  (128 * WT_STRIDE)
#define LIN1_SMEM_BYTES ((XS_ELEMS + WT_ELEMS) * (int)sizeof(float))

// -------- fused linear via 3xTF32 tensor cores --------
__global__ __launch_bounds__(128) void lin1_mma_kernel(
    const float* __restrict__ x,
    const float* __restrict__ W1l,
    const float* __restrict__ W1r,
    int n)
{
    extern __shared__ float smem[];
    float (*xs)[XS_STRIDE] = (float (*)[XS_STRIDE])smem;              // 64 x 132
    float (*wt)[WT_STRIDE] = (float (*)[WT_STRIDE])(smem + XS_ELEMS); // 128 x 72

    int tid = threadIdx.x;
    int node0 = blockIdx.x * 64;

    for (int idx = tid; idx < DD * 64; idx += 128) {
        int k = idx & 127, j = idx >> 7;
        wt[k][j] = (j < HH) ? W1l[j * DD + k] : W1r[(j - HH) * DD + k];
    }
    for (int idx = tid; idx < 64 * (DD / 4); idx += 128) {
        int r = idx >> 5, c4 = idx & 31;
        float4 v = (node0 + r < n)
                 ? ((const float4*)(x + (size_t)(node0 + r) * DD))[c4]
                 : make_float4(0.f, 0.f, 0.f, 0.f);
        *(float4*)&xs[r][c4 * 4] = v;
    }
    __syncthreads();

    int warp = tid >> 5, lane = tid & 31;
    int g = lane >> 2, tig = lane & 3;
    int m0 = warp * 16;

    float acc[8][4];
#pragma unroll
    for (int nt = 0; nt < 8; nt++)
#pragma unroll
        for (int c = 0; c < 4; c++) acc[nt][c] = 0.0f;

#pragma unroll
    for (int kc = 0; kc < 16; kc++) {
        int k0 = kc * 8;
        float a0 = xs[m0 + g][k0 + tig];
        float a1 = xs[m0 + g + 8][k0 + tig];
        float a2 = xs[m0 + g][k0 + tig + 4];
        float a3 = xs[m0 + g + 8][k0 + tig + 4];
        unsigned ah0, al0, ah1, al1, ah2, al2, ah3, al3;
        split_tf32(a0, ah0, al0); split_tf32(a1, ah1, al1);
        split_tf32(a2, ah2, al2); split_tf32(a3, ah3, al3);

#pragma unroll
        for (int nt = 0; nt < 8; nt++) {
            float b0f = wt[k0 + tig][nt * 8 + g];
            float b1f = wt[k0 + tig + 4][nt * 8 + g];
            unsigned bh0, bl0, bh1, bl1;
            split_tf32(b0f, bh0, bl0); split_tf32(b1f, bh1, bl1);
            mma_tf32(acc[nt], ah0, ah1, ah2, ah3, bh0, bh1);  // hi*hi
            mma_tf32(acc[nt], al0, al1, al2, al3, bh0, bh1);  // lo*hi
            mma_tf32(acc[nt], ah0, ah1, ah2, ah3, bl0, bl1);  // hi*lo
        }
    }

    int node_a = node0 + m0 + g;
    int node_b = node_a + 8;
#pragma unroll
    for (int nt = 0; nt < 8; nt++) {
        int j = nt * 8 + 2 * tig;
        float* base = (j < HH) ? g_y1 : g_z1;
        int jj = j & 31;
        if (node_a < n) *(float2*)&base[node_a * HH + jj] = make_float2(acc[nt][0], acc[nt][1]);
        if (node_b < n) *(float2*)&base[node_b * HH + jj] = make_float2(acc[nt][2], acc[nt][3]);
    }
}

// -------- fused gather-aggregate + epilogue + layer-2 linear (warp/node) --------
// Lanes cooperatively load up to 32 neighbor indices (coalesced), broadcast
// via shfl; each neighbor is one 128B coalesced row gather (L2-resident).
__global__ __launch_bounds__(256) void aggepi_kernel(
    const float* __restrict__ b1,
    const float* __restrict__ W2l,
    const float* __restrict__ W2r,
    int n)
{
    __shared__ float sb1[HH], swl[HH], swr[HH];
    if (threadIdx.x < HH) {
        sb1[threadIdx.x] = b1[threadIdx.x];
        swl[threadIdx.x] = W2l[threadIdx.x];
        swr[threadIdx.x] = W2r[threadIdx.x];
    }
    __syncthreads();
    int node = (blockIdx.x * blockDim.x + threadIdx.x) >> 5;
    int lane = threadIdx.x & 31;
    if (node >= n) return;

    int beg = g_rowptr[node], end = g_rowptr[node + 1];
    float acc = 0.0f;
    for (int c = beg; c < end; c += 32) {
        int j = c + lane;
        int idx = (j < end) ? g_esrc[j] : 0;
        int m = end - c; if (m > 32) m = 32;
        for (int i = 0; i < m; i++) {
            int s = __shfl_sync(0xFFFFFFFFu, idx, i);
            acc += g_y1[s * HH + lane];
        }
    }

    float deg = (float)(end - beg);
    float rdeg = 1.0f / fmaxf(deg, 1.0f);
    float hv = fmaxf(fmaf(acc, rdeg, sb1[lane] + g_z1[node * HH + lane]), 0.0f);
    float sl = hv * swl[lane];
    float sr = hv * swr[lane];
#pragma unroll
    for (int o = 16; o; o >>= 1) {
        sl += __shfl_xor_sync(0xFFFFFFFFu, sl, o);
        sr += __shfl_xor_sync(0xFFFFFFFFu, sr, o);
    }
    if (lane == 0) { g_sl[node] = sl; g_sr[node] = sr; }
}

// -------- fused layer-2 gather + final sigmoid (thread/node, 4-unrolled) -----
__global__ __launch_bounds__(256) void gather2_kernel(const float* __restrict__ b2,
                                                      float* __restrict__ out, int n) {
    int i = blockIdx.x * blockDim.x + threadIdx.x;
    if (i >= n) return;
    int beg = g_rowptr[i], end = g_rowptr[i + 1];
    float a = 0.0f;
    int j = beg;
    for (; j + 4 <= end; j += 4) {
        int s0 = g_esrc[j], s1 = g_esrc[j + 1], s2 = g_esrc[j + 2], s3 = g_esrc[j + 3];
        a += (g_sl[s0] + g_sl[s1]) + (g_sl[s2] + g_sl[s3]);
    }
    for (; j < end; j++) a += g_sl[g_esrc[j]];
    float rdeg = 1.0f / fmaxf((float)(end - beg), 1.0f);
    float v = fmaf(a, rdeg, b2[0] + g_sr[i]);
    out[i] = 1.0f / (1.0f + expf(-v));
}

extern "C" void kernel_launch(void* const* d_in, const int* in_sizes, int n_in,
                              void* d_out, int out_size) {
    const float* x   = (const float*)d_in[0];
    const void*  ei  = d_in[1];
    const float* W1l = (const float*)d_in[2];
    const float* b1  = (const float*)d_in[3];
    const float* W1r = (const float*)d_in[4];
    const float* W2l = (const float*)d_in[5];
    const float* b2  = (const float*)d_in[6];
    const float* W2r = (const float*)d_in[7];
    float* out = (float*)d_out;

    int n = in_sizes[0] / DD;            // 50000
    long long E = in_sizes[1] / 2;       // 800000
    int nb = (n + 255) / 256;            // 196 scan blocks

    cudaFuncSetAttribute(lin1_mma_kernel,
                         cudaFuncAttributeMaxDynamicSharedMemorySize,
                         LIN1_SMEM_BYTES);

    init_kernel<<<64, 256>>>((const unsigned*)ei, n);
    {
        long long Q = (E + 1) >> 1;
        hist_kernel<<<(unsigned)((Q + 255) / 256), 256>>>(ei, E);
    }
    scanA_kernel<<<nb, 256>>>(n);
    scanB_kernel<<<1, 256>>>(nb, n, (int)E);
    scanC_kernel<<<nb, 256>>>(n);
    {
        long long Q = (E + 3) >> 2;
        reorder_kernel<<<(unsigned)((Q + 255) / 256), 256>>>(ei, E);
    }
    lin1_mma_kernel<<<(n + 63) / 64, 128, LIN1_SMEM_BYTES>>>(x, W1l, W1r, n);
    aggepi_kernel<<<(n * 32 + 255) / 256, 256>>>(b1, W2l, W2r, n);
    gather2_kernel<<<(n + 255) / 256, 256>>>(b2, out, n);
}

// round 11
// speedup vs baseline: 1.3817x; 1.3817x over previous
#include <cuda_runtime.h>
#include <cuda_bf16.h>

// Problem constants (fixed shapes for this problem)
#define NN 50000
#define EE 800000
#define DD 128
#define HH 32

// -------- scratch (no allocations allowed) --------
__device__ __align__(16) float g_y1[NN * HH];    // x @ W1_l^T
__device__ __align__(16) float g_z1[NN * HH];    // x @ W1_r^T
__device__ __align__(16) float g_agg[NN * HH];   // scatter-sum of y1
__device__ __align__(16) float g_deg[NN];
__device__ __align__(16) float g_sl[NN];         // h @ W2_l^T
__device__ __align__(16) float g_sr[NN];         // h @ W2_r^T
__device__ __align__(16) float g_agg2[NN];       // scatter-sum of s_l
__device__ int   g_is64;                         // edge_index dtype flag

// load node index (always < 2^31) as 32-bit regardless of storage width
__device__ __forceinline__ int edge_at32(const void* ei, long long pos, int is64) {
    return is64 ? ((const int*)ei)[2 * pos] : ((const int*)ei)[pos];
}

// -------- init: detect dtype (block 0) + zero accumulators (vectorized) --------
__global__ void init_kernel(const unsigned* __restrict__ ei_words, int n) {
    if (blockIdx.x == 0) {
        __shared__ int flag;
        if (threadIdx.x == 0) flag = 1;
        __syncthreads();
        unsigned w = ei_words[2 * threadIdx.x + 1];  // high words if int64
        if (w != 0u) flag = 0;
        __syncthreads();
        if (threadIdx.x == 0) g_is64 = flag;
    }
    float4 z4 = make_float4(0.f, 0.f, 0.f, 0.f);
    int n_agg4 = n * HH / 4;
    float4* agg4 = (float4*)g_agg;
    for (int i = blockIdx.x * blockDim.x + threadIdx.x; i < n_agg4;
         i += gridDim.x * blockDim.x)
        agg4[i] = z4;
    for (int i = blockIdx.x * blockDim.x + threadIdx.x; i < n;
         i += gridDim.x * blockDim.x) {
        g_deg[i] = 0.0f;
        g_agg2[i] = 0.0f;
    }
}

// -------- tf32 helpers --------
__device__ __forceinline__ float f2tf32f(float f) {
    unsigned u;
    asm("cvt.rna.tf32.f32 %0, %1;" : "=r"(u) : "f"(f));
    return __uint_as_float(u);
}
__device__ __forceinline__ void mma_tf32(float* d, unsigned a0, unsigned a1,
                                         unsigned a2, unsigned a3,
                                         unsigned b0, unsigned b1) {
    asm volatile(
        "mma.sync.aligned.m16n8k8.row.col.f32.tf32.tf32.f32 "
        "{%0,%1,%2,%3}, {%4,%5,%6,%7}, {%8,%9}, {%0,%1,%2,%3};\n"
        : "+f"(d[0]), "+f"(d[1]), "+f"(d[2]), "+f"(d[3])
        : "r"(a0), "r"(a1), "r"(a2), "r"(a3), "r"(b0), "r"(b1));
}

// Dynamic smem layout: xs[64][132] then wt[128][72]
#define XS_STRIDE 132
#define WT_STRIDE 72
#define XS_ELEMS  (64 * XS_STRIDE)
#define WT_ELEMS  (128 * WT_STRIDE)
#define LIN1_SMEM_BYTES ((XS_ELEMS + WT_ELEMS) * (int)sizeof(float))

// -------- fused linear via single-pass TF32 tensor cores --------
// x and W rounded to tf32 during smem fill; inner loop is pure LDS + MMA.
__global__ __launch_bounds__(128) void lin1_mma_kernel(
    const float* __restrict__ x,
    const float* __restrict__ W1l,
    const float* __restrict__ W1r,
    int n)
{
    extern __shared__ float smem[];
    float (*xs)[XS_STRIDE] = (float (*)[XS_STRIDE])smem;              // 64 x 132
    float (*wt)[WT_STRIDE] = (float (*)[WT_STRIDE])(smem + XS_ELEMS); // 128 x 72

    int tid = threadIdx.x;
    int node0 = blockIdx.x * 64;

    for (int idx = tid; idx < DD * 64; idx += 128) {
        int k = idx & 127, j = idx >> 7;
        float w = (j < HH) ? W1l[j * DD + k] : W1r[(j - HH) * DD + k];
        wt[k][j] = f2tf32f(w);
    }
    for (int idx = tid; idx < 64 * (DD / 4); idx += 128) {
        int r = idx >> 5, c4 = idx & 31;
        float4 v = (node0 + r < n)
                 ? ((const float4*)(x + (size_t)(node0 + r) * DD))[c4]
                 : make_float4(0.f, 0.f, 0.f, 0.f);
        v.x = f2tf32f(v.x); v.y = f2tf32f(v.y);
        v.z = f2tf32f(v.z); v.w = f2tf32f(v.w);
        *(float4*)&xs[r][c4 * 4] = v;
    }
    __syncthreads();

    int warp = tid >> 5, lane = tid & 31;
    int g = lane >> 2, tig = lane & 3;
    int m0 = warp * 16;

    float acc[8][4];
#pragma unroll
    for (int nt = 0; nt < 8; nt++)
#pragma unroll
        for (int c = 0; c < 4; c++) acc[nt][c] = 0.0f;

#pragma unroll
    for (int kc = 0; kc < 16; kc++) {
        int k0 = kc * 8;
        unsigned a0 = __float_as_uint(xs[m0 + g][k0 + tig]);
        unsigned a1 = __float_as_uint(xs[m0 + g + 8][k0 + tig]);
        unsigned a2 = __float_as_uint(xs[m0 + g][k0 + tig + 4]);
        unsigned a3 = __float_as_uint(xs[m0 + g + 8][k0 + tig + 4]);

#pragma unroll
        for (int nt = 0; nt < 8; nt++) {
            unsigned b0 = __float_as_uint(wt[k0 + tig][nt * 8 + g]);
            unsigned b1 = __float_as_uint(wt[k0 + tig + 4][nt * 8 + g]);
            mma_tf32(acc[nt], a0, a1, a2, a3, b0, b1);
        }
    }

    int node_a = node0 + m0 + g;
    int node_b = node_a + 8;
#pragma unroll
    for (int nt = 0; nt < 8; nt++) {
        int j = nt * 8 + 2 * tig;
        float* base = (j < HH) ? g_y1 : g_z1;
        int jj = j & 31;
        if (node_a < n) *(float2*)&base[node_a * HH + jj] = make_float2(acc[nt][0], acc[nt][1]);
        if (node_b < n) *(float2*)&base[node_b * HH + jj] = make_float2(acc[nt][2], acc[nt][3]);
    }
}

// -------- layer-1 edge scatter: cooperative 8-edges-per-8-lane-group --------
__global__ __launch_bounds__(256) void scatter1_kernel(const void* __restrict__ ei, long long E) {
    long long t = (long long)blockIdx.x * blockDim.x + threadIdx.x;
    long long base = (t >> 3) * 8;       // first edge of this group
    int sub = (int)(t & 7);              // this lane's feature chunk
    int is64 = g_is64;

    long long my_e = base + sub;
    int my_src = 0, my_dst = 0;
    bool my_valid = (my_e < E);
    if (my_valid) {
        my_src = edge_at32(ei, my_e, is64);
        my_dst = edge_at32(ei, E + my_e, is64);
    }
    int lane = threadIdx.x & 31;
    int gbase = lane & ~7;               // leader lane of this 8-group

#pragma unroll
    for (int i = 0; i < 8; i++) {
        int s = __shfl_sync(0xFFFFFFFFu, my_src, gbase + i);
        int d = __shfl_sync(0xFFFFFFFFu, my_dst, gbase + i);
        if (base + i < E) {
            float4 v = *(const float4*)&g_y1[s * HH + sub * 4];
            atomicAdd((float4*)&g_agg[d * HH + sub * 4], v);
        }
    }
    if (my_valid) atomicAdd(&g_deg[my_dst], 1.0f);
}

// -------- layer-1 epilogue + layer-2 linear: 8 threads/node --------
__global__ __launch_bounds__(256) void epi_kernel(
    const float* __restrict__ b1,
    const float* __restrict__ W2l,
    const float* __restrict__ W2r,
    int n)
{
    __shared__ float sb1[HH], swl[HH], swr[HH];
    if (threadIdx.x < HH) {
        sb1[threadIdx.x] = b1[threadIdx.x];
        swl[threadIdx.x] = W2l[threadIdx.x];
        swr[threadIdx.x] = W2r[threadIdx.x];
    }
    __syncthreads();
    int t = blockIdx.x * blockDim.x + threadIdx.x;
    int node = t >> 3;         // 8 threads per node
    int q = t & 7;             // 4-feature slice
    bool valid = (node < n);
    int nd = valid ? node : (n - 1);   // clamp (keep full warp for shfl)

    float4 a = *(const float4*)&g_agg[(size_t)nd * HH + q * 4];
    float4 z = *(const float4*)&g_z1[(size_t)nd * HH + q * 4];
    float rdeg = 1.0f / fmaxf(g_deg[nd], 1.0f);
    int k = q * 4;
    float h0 = fmaxf(fmaf(a.x, rdeg, sb1[k + 0] + z.x), 0.0f);
    float h1 = fmaxf(fmaf(a.y, rdeg, sb1[k + 1] + z.y), 0.0f);
    float h2 = fmaxf(fmaf(a.z, rdeg, sb1[k + 2] + z.z), 0.0f);
    float h3 = fmaxf(fmaf(a.w, rdeg, sb1[k + 3] + z.w), 0.0f);
    float sl = h0 * swl[k + 0] + h1 * swl[k + 1] + h2 * swl[k + 2] + h3 * swl[k + 3];
    float sr = h0 * swr[k + 0] + h1 * swr[k + 1] + h2 * swr[k + 2] + h3 * swr[k + 3];
    sl += __shfl_xor_sync(0xFFFFFFFFu, sl, 1);
    sr += __shfl_xor_sync(0xFFFFFFFFu, sr, 1);
    sl += __shfl_xor_sync(0xFFFFFFFFu, sl, 2);
    sr += __shfl_xor_sync(0xFFFFFFFFu, sr, 2);
    sl += __shfl_xor_sync(0xFFFFFFFFu, sl, 4);
    sr += __shfl_xor_sync(0xFFFFFFFFu, sr, 4);
    if (valid && q == 0) { g_sl[node] = sl; g_sr[node] = sr; }
}

// -------- layer-2 edge scatter: agg2[dst] += s_l[src], 2 edges/thread --------
__global__ __launch_bounds__(256) void scatter2_kernel(const void* __restrict__ ei, long long E) {
    long long t = (long long)blockIdx.x * blockDim.x + threadIdx.x;
    long long half = (E + 1) >> 1;
    if (t >= half) return;
    int is64 = g_is64;
    long long e0 = t;
    long long e1 = t + half;
    int s0 = edge_at32(ei, e0, is64);
    int d0 = edge_at32(ei, E + e0, is64);
    float v0 = g_sl[s0];
    if (e1 < E) {
        int s1 = edge_at32(ei, e1, is64);
        int d1 = edge_at32(ei, E + e1, is64);
        float v1 = g_sl[s1];
        atomicAdd(&g_agg2[d0], v0);
        atomicAdd(&g_agg2[d1], v1);
    } else {
        atomicAdd(&g_agg2[d0], v0);
    }
}

// -------- final: sigmoid(agg2/deg + b2 + s_r) --------
__global__ __launch_bounds__(256) void final_kernel(const float* __restrict__ b2,
                                                    float* __restrict__ out, int n) {
    int i = blockIdx.x * blockDim.x + threadIdx.x;
    if (i >= n) return;
    float rdeg = 1.0f / fmaxf(g_deg[i], 1.0f);
    float v = fmaf(g_agg2[i], rdeg, b2[0] + g_sr[i]);
    out[i] = 1.0f / (1.0f + expf(-v));
}

extern "C" void kernel_launch(void* const* d_in, const int* in_sizes, int n_in,
                              void* d_out, int out_size) {
    const float* x   = (const float*)d_in[0];
    const void*  ei  = d_in[1];
    const float* W1l = (const float*)d_in[2];
    const float* b1  = (const float*)d_in[3];
    const float* W1r = (const float*)d_in[4];
    const float* W2l = (const float*)d_in[5];
    const float* b2  = (const float*)d_in[6];
    const float* W2r = (const float*)d_in[7];
    float* out = (float*)d_out;

    int n = in_sizes[0] / DD;            // 50000
    long long E = in_sizes[1] / 2;       // 800000

    cudaFuncSetAttribute(lin1_mma_kernel,
                         cudaFuncAttributeMaxDynamicSharedMemorySize,
                         LIN1_SMEM_BYTES);

    init_kernel<<<512, 256>>>((const unsigned*)ei, n);
    lin1_mma_kernel<<<(n + 63) / 64, 128, LIN1_SMEM_BYTES>>>(x, W1l, W1r, n);
    {
        long long threads = ((E + 7) >> 3) << 3;   // one thread per edge, groups of 8
        scatter1_kernel<<<(unsigned)((threads + 255) / 256), 256>>>(ei, E);
    }
    epi_kernel<<<(n * 8 + 255) / 256, 256>>>(b1, W2l, W2r, n);
    {
        long long half = (E + 1) >> 1;
        scatter2_kernel<<<(unsigned)((half + 255) / 256), 256>>>(ei, E);
    }
    final_kernel<<<(n + 255) / 256, 256>>>(b2, out, n);
}

// round 12
// speedup vs baseline: 1.3824x; 1.0005x over previous
#include <cuda_runtime.h>
#include <cuda_bf16.h>

// Problem constants (fixed shapes for this problem)
#define NN 50000
#define EE 800000
#define DD 128
#define HH 32

// -------- scratch (no allocations allowed) --------
__device__ __align__(16) float g_y1[NN * HH];    // x @ W1_l^T
__device__ __align__(16) float g_z1[NN * HH];    // x @ W1_r^T
__device__ __align__(16) float g_agg[NN * HH];   // scatter-sum of y1
__device__ __align__(16) float g_deg[NN];
__device__ __align__(16) float g_sl[NN];         // h @ W2_l^T
__device__ __align__(16) float g_sr[NN];         // h @ W2_r^T
__device__ __align__(16) float g_agg2[NN];       // scatter-sum of s_l
__device__ int   g_is64;                         // edge_index dtype flag

// load node index (always < 2^31) as 32-bit regardless of storage width
__device__ __forceinline__ int edge_at32(const void* ei, long long pos, int is64) {
    return is64 ? ((const int*)ei)[2 * pos] : ((const int*)ei)[pos];
}

// -------- tf32 helpers --------
__device__ __forceinline__ float f2tf32f(float f) {
    unsigned u;
    asm("cvt.rna.tf32.f32 %0, %1;" : "=r"(u) : "f"(f));
    return __uint_as_float(u);
}
__device__ __forceinline__ void mma_tf32(float* d, unsigned a0, unsigned a1,
                                         unsigned a2, unsigned a3,
                                         unsigned b0, unsigned b1) {
    asm volatile(
        "mma.sync.aligned.m16n8k8.row.col.f32.tf32.tf32.f32 "
        "{%0,%1,%2,%3}, {%4,%5,%6,%7}, {%8,%9}, {%0,%1,%2,%3};\n"
        : "+f"(d[0]), "+f"(d[1]), "+f"(d[2]), "+f"(d[3])
        : "r"(a0), "r"(a1), "r"(a2), "r"(a3), "r"(b0), "r"(b1));
}

// Dynamic smem layout: xs[64][132] then wt[128][72]
#define XS_STRIDE 132
#define WT_STRIDE 72
#define XS_ELEMS  (64 * XS_STRIDE)
#define WT_ELEMS  (128 * WT_STRIDE)
#define LIN1_SMEM_BYTES ((XS_ELEMS + WT_ELEMS) * (int)sizeof(float))

// -------- fused: init (zero accumulators, dtype detect) + tf32 MMA linear ----
// Each block also zeroes the accumulator slices for its 64 nodes; block 0
// performs the edge dtype detection. Removes the standalone init kernel.
__global__ __launch_bounds__(128) void lin1_mma_kernel(
    const float* __restrict__ x,
    const float* __restrict__ W1l,
    const float* __restrict__ W1r,
    const unsigned* __restrict__ ei_words,
    int n)
{
    extern __shared__ float smem[];
    float (*xs)[XS_STRIDE] = (float (*)[XS_STRIDE])smem;              // 64 x 132
    float (*wt)[WT_STRIDE] = (float (*)[WT_STRIDE])(smem + XS_ELEMS); // 128 x 72

    int tid = threadIdx.x;
    int node0 = blockIdx.x * 64;

    // ---- folded init duties ----
    if (blockIdx.x == 0) {
        __shared__ int flag;
        if (tid == 0) flag = 1;
        __syncthreads();
        unsigned w = ei_words[2 * tid + 1];  // high words if int64
        if (w != 0u) flag = 0;
        __syncthreads();
        if (tid == 0) g_is64 = flag;
    }
    {
        // zero g_agg rows for this block's 64 nodes: 512 float4
        float4 z4 = make_float4(0.f, 0.f, 0.f, 0.f);
        int lim = n - node0; if (lim > 64) lim = 64;
        int q4 = lim * (HH / 4);                  // float4 count
        float4* aggp = (float4*)&g_agg[(size_t)node0 * HH];
        for (int i = tid; i < q4; i += 128) aggp[i] = z4;
        for (int i = tid; i < lim; i += 128) {
            g_deg[node0 + i] = 0.0f;
            g_agg2[node0 + i] = 0.0f;
        }
    }

    // ---- weight + x tiles (rounded to tf32 in smem) ----
    for (int idx = tid; idx < DD * 64; idx += 128) {
        int k = idx & 127, j = idx >> 7;
        float w = (j < HH) ? W1l[j * DD + k] : W1r[(j - HH) * DD + k];
        wt[k][j] = f2tf32f(w);
    }
    for (int idx = tid; idx < 64 * (DD / 4); idx += 128) {
        int r = idx >> 5, c4 = idx & 31;
        float4 v = (node0 + r < n)
                 ? ((const float4*)(x + (size_t)(node0 + r) * DD))[c4]
                 : make_float4(0.f, 0.f, 0.f, 0.f);
        v.x = f2tf32f(v.x); v.y = f2tf32f(v.y);
        v.z = f2tf32f(v.z); v.w = f2tf32f(v.w);
        *(float4*)&xs[r][c4 * 4] = v;
    }
    __syncthreads();

    int warp = tid >> 5, lane = tid & 31;
    int g = lane >> 2, tig = lane & 3;
    int m0 = warp * 16;

    float acc[8][4];
#pragma unroll
    for (int nt = 0; nt < 8; nt++)
#pragma unroll
        for (int c = 0; c < 4; c++) acc[nt][c] = 0.0f;

#pragma unroll
    for (int kc = 0; kc < 16; kc++) {
        int k0 = kc * 8;
        unsigned a0 = __float_as_uint(xs[m0 + g][k0 + tig]);
        unsigned a1 = __float_as_uint(xs[m0 + g + 8][k0 + tig]);
        unsigned a2 = __float_as_uint(xs[m0 + g][k0 + tig + 4]);
        unsigned a3 = __float_as_uint(xs[m0 + g + 8][k0 + tig + 4]);

#pragma unroll
        for (int nt = 0; nt < 8; nt++) {
            unsigned b0 = __float_as_uint(wt[k0 + tig][nt * 8 + g]);
            unsigned b1 = __float_as_uint(wt[k0 + tig + 4][nt * 8 + g]);
            mma_tf32(acc[nt], a0, a1, a2, a3, b0, b1);
        }
    }

    int node_a = node0 + m0 + g;
    int node_b = node_a + 8;
#pragma unroll
    for (int nt = 0; nt < 8; nt++) {
        int j = nt * 8 + 2 * tig;
        float* base = (j < HH) ? g_y1 : g_z1;
        int jj = j & 31;
        if (node_a < n) *(float2*)&base[node_a * HH + jj] = make_float2(acc[nt][0], acc[nt][1]);
        if (node_b < n) *(float2*)&base[node_b * HH + jj] = make_float2(acc[nt][2], acc[nt][3]);
    }
}

// -------- layer-1 edge scatter: cooperative 8-edges-per-8-lane-group --------
__global__ __launch_bounds__(256) void scatter1_kernel(const void* __restrict__ ei, long long E) {
    long long t = (long long)blockIdx.x * blockDim.x + threadIdx.x;
    long long base = (t >> 3) * 8;       // first edge of this group
    int sub = (int)(t & 7);              // this lane's feature chunk
    int is64 = g_is64;

    long long my_e = base + sub;
    int my_src = 0, my_dst = 0;
    bool my_valid = (my_e < E);
    if (my_valid) {
        my_src = edge_at32(ei, my_e, is64);
        my_dst = edge_at32(ei, E + my_e, is64);
    }
    int lane = threadIdx.x & 31;
    int gbase = lane & ~7;               // leader lane of this 8-group

#pragma unroll
    for (int i = 0; i < 8; i++) {
        int s = __shfl_sync(0xFFFFFFFFu, my_src, gbase + i);
        int d = __shfl_sync(0xFFFFFFFFu, my_dst, gbase + i);
        if (base + i < E) {
            float4 v = *(const float4*)&g_y1[s * HH + sub * 4];
            atomicAdd((float4*)&g_agg[d * HH + sub * 4], v);
        }
    }
    if (my_valid) atomicAdd(&g_deg[my_dst], 1.0f);
}

// -------- layer-1 epilogue + layer-2 linear: 8 threads/node --------
__global__ __launch_bounds__(256) void epi_kernel(
    const float* __restrict__ b1,
    const float* __restrict__ W2l,
    const float* __restrict__ W2r,
    int n)
{
    __shared__ float sb1[HH], swl[HH], swr[HH];
    if (threadIdx.x < HH) {
        sb1[threadIdx.x] = b1[threadIdx.x];
        swl[threadIdx.x] = W2l[threadIdx.x];
        swr[threadIdx.x] = W2r[threadIdx.x];
    }
    __syncthreads();
    int t = blockIdx.x * blockDim.x + threadIdx.x;
    int node = t >> 3;         // 8 threads per node
    int q = t & 7;             // 4-feature slice
    bool valid = (node < n);
    int nd = valid ? node : (n - 1);   // clamp (keep full warp for shfl)

    float4 a = *(const float4*)&g_agg[(size_t)nd * HH + q * 4];
    float4 z = *(const float4*)&g_z1[(size_t)nd * HH + q * 4];
    float rdeg = 1.0f / fmaxf(g_deg[nd], 1.0f);
    int k = q * 4;
    float h0 = fmaxf(fmaf(a.x, rdeg, sb1[k + 0] + z.x), 0.0f);
    float h1 = fmaxf(fmaf(a.y, rdeg, sb1[k + 1] + z.y), 0.0f);
    float h2 = fmaxf(fmaf(a.z, rdeg, sb1[k + 2] + z.z), 0.0f);
    float h3 = fmaxf(fmaf(a.w, rdeg, sb1[k + 3] + z.w), 0.0f);
    float sl = h0 * swl[k + 0] + h1 * swl[k + 1] + h2 * swl[k + 2] + h3 * swl[k + 3];
    float sr = h0 * swr[k + 0] + h1 * swr[k + 1] + h2 * swr[k + 2] + h3 * swr[k + 3];
    sl += __shfl_xor_sync(0xFFFFFFFFu, sl, 1);
    sr += __shfl_xor_sync(0xFFFFFFFFu, sr, 1);
    sl += __shfl_xor_sync(0xFFFFFFFFu, sl, 2);
    sr += __shfl_xor_sync(0xFFFFFFFFu, sr, 2);
    sl += __shfl_xor_sync(0xFFFFFFFFu, sl, 4);
    sr += __shfl_xor_sync(0xFFFFFFFFu, sr, 4);
    if (valid && q == 0) { g_sl[node] = sl; g_sr[node] = sr; }
}

// -------- layer-2 edge scatter: agg2[dst] += s_l[src], 4 edges/thread --------
__global__ __launch_bounds__(256) void scatter2_kernel(const void* __restrict__ ei, long long E) {
    long long t = (long long)blockIdx.x * blockDim.x + threadIdx.x;
    long long Q = (E + 3) >> 2;
    if (t >= Q) return;
    int is64 = g_is64;
    int s[4], d[4];
    bool ok[4];
#pragma unroll
    for (int k = 0; k < 4; k++) {
        long long e = t + k * Q;
        ok[k] = (e < E);
        if (ok[k]) {
            s[k] = edge_at32(ei, e, is64);
            d[k] = edge_at32(ei, E + e, is64);
        }
    }
    float v[4];
#pragma unroll
    for (int k = 0; k < 4; k++)
        if (ok[k]) v[k] = g_sl[s[k]];
#pragma unroll
    for (int k = 0; k < 4; k++)
        if (ok[k]) atomicAdd(&g_agg2[d[k]], v[k]);
}

// -------- final: sigmoid(agg2/deg + b2 + s_r) --------
__global__ __launch_bounds__(256) void final_kernel(const float* __restrict__ b2,
                                                    float* __restrict__ out, int n) {
    int i = blockIdx.x * blockDim.x + threadIdx.x;
    if (i >= n) return;
    float rdeg = 1.0f / fmaxf(g_deg[i], 1.0f);
    float v = fmaf(g_agg2[i], rdeg, b2[0] + g_sr[i]);
    out[i] = 1.0f / (1.0f + expf(-v));
}

extern "C" void kernel_launch(void* const* d_in, const int* in_sizes, int n_in,
                              void* d_out, int out_size) {
    const float* x   = (const float*)d_in[0];
    const void*  ei  = d_in[1];
    const float* W1l = (const float*)d_in[2];
    const float* b1  = (const float*)d_in[3];
    const float* W1r = (const float*)d_in[4];
    const float* W2l = (const float*)d_in[5];
    const float* b2  = (const float*)d_in[6];
    const float* W2r = (const float*)d_in[7];
    float* out = (float*)d_out;

    int n = in_sizes[0] / DD;            // 50000
    long long E = in_sizes[1] / 2;       // 800000

    cudaFuncSetAttribute(lin1_mma_kernel,
                         cudaFuncAttributeMaxDynamicSharedMemorySize,
                         LIN1_SMEM_BYTES);

    lin1_mma_kernel<<<(n + 63) / 64, 128, LIN1_SMEM_BYTES>>>(
        x, W1l, W1r, (const unsigned*)ei, n);
    {
        long long threads = ((E + 7) >> 3) << 3;   // one thread per edge, groups of 8
        scatter1_kernel<<<(unsigned)((threads + 255) / 256), 256>>>(ei, E);
    }
    epi_kernel<<<(n * 8 + 255) / 256, 256>>>(b1, W2l, W2r, n);
    {
        long long Q = (E + 3) >> 2;
        scatter2_kernel<<<(unsigned)((Q + 255) / 256), 256>>>(ei, E);
    }
    final_kernel<<<(n + 255) / 256, 256>>>(b2, out, n);
}

// round 14
// speedup vs baseline: 1.4182x; 1.0259x over previous
#include <cuda_runtime.h>
#include <cuda_bf16.h>

// Problem constants (fixed shapes for this problem)
#define NN 50000
#define EE 800000
#define DD 128
#define HH 32

// -------- scratch (no allocations allowed) --------
__device__ __align__(16) float g_y1[NN * HH];    // x @ W1_l^T
__device__ __align__(16) float g_z1[NN * HH];    // x @ W1_r^T
__device__ __align__(16) float g_agg[NN * HH];   // scatter-sum of y1
__device__ __align__(16) float g_deg[NN];
__device__ __align__(16) float g_sl[NN];         // h @ W2_l^T
__device__ __align__(16) float g_sr[NN];         // h @ W2_r^T
__device__ __align__(16) float g_agg2[NN];       // scatter-sum of s_l
__device__ int   g_is64;                         // edge_index dtype flag

// load node index (always < 2^31) as 32-bit regardless of storage width
__device__ __forceinline__ int edge_at32(const void* ei, long long pos, int is64) {
    return is64 ? ((const int*)ei)[2 * pos] : ((const int*)ei)[pos];
}

// -------- tf32 helpers --------
__device__ __forceinline__ float f2tf32f(float f) {
    unsigned u;
    asm("cvt.rna.tf32.f32 %0, %1;" : "=r"(u) : "f"(f));
    return __uint_as_float(u);
}
__device__ __forceinline__ void mma_tf32(float* d, unsigned a0, unsigned a1,
                                         unsigned a2, unsigned a3,
                                         unsigned b0, unsigned b1) {
    asm volatile(
        "mma.sync.aligned.m16n8k8.row.col.f32.tf32.tf32.f32 "
        "{%0,%1,%2,%3}, {%4,%5,%6,%7}, {%8,%9}, {%0,%1,%2,%3};\n"
        : "+f"(d[0]), "+f"(d[1]), "+f"(d[2]), "+f"(d[3])
        : "r"(a0), "r"(a1), "r"(a2), "r"(a3), "r"(b0), "r"(b1));
}

// Dynamic smem layout: xs[64][132] then wt[128][72]
#define XS_STRIDE 132
#define WT_STRIDE 72
#define XS_ELEMS  (64 * XS_STRIDE)
#define WT_ELEMS  (128 * WT_STRIDE)
#define LIN1_SMEM_BYTES ((XS_ELEMS + WT_ELEMS) * (int)sizeof(float))

// -------- fused: init (zero accumulators, dtype detect) + tf32 MMA linear ----
__global__ __launch_bounds__(128) void lin1_mma_kernel(
    const float* __restrict__ x,
    const float* __restrict__ W1l,
    const float* __restrict__ W1r,
    const unsigned* __restrict__ ei_words,
    int n)
{
    extern __shared__ float smem[];
    float (*xs)[XS_STRIDE] = (float (*)[XS_STRIDE])smem;              // 64 x 132
    float (*wt)[WT_STRIDE] = (float (*)[WT_STRIDE])(smem + XS_ELEMS); // 128 x 72

    int tid = threadIdx.x;
    int node0 = blockIdx.x * 64;

    // ---- folded init duties ----
    if (blockIdx.x == 0) {
        __shared__ int flag;
        if (tid == 0) flag = 1;
        __syncthreads();
        unsigned w = ei_words[2 * tid + 1];  // high words if int64
        if (w != 0u) flag = 0;
        __syncthreads();
        if (tid == 0) g_is64 = flag;
    }
    {
        float4 z4 = make_float4(0.f, 0.f, 0.f, 0.f);
        int lim = n - node0; if (lim > 64) lim = 64;
        int q4 = lim * (HH / 4);
        float4* aggp = (float4*)&g_agg[(size_t)node0 * HH];
        for (int i = tid; i < q4; i += 128) aggp[i] = z4;
        for (int i = tid; i < lim; i += 128) {
            g_deg[node0 + i] = 0.0f;
            g_agg2[node0 + i] = 0.0f;
        }
    }

    // ---- weight + x tiles (rounded to tf32 in smem) ----
    for (int idx = tid; idx < DD * 64; idx += 128) {
        int k = idx & 127, j = idx >> 7;
        float w = (j < HH) ? W1l[j * DD + k] : W1r[(j - HH) * DD + k];
        wt[k][j] = f2tf32f(w);
    }
    for (int idx = tid; idx < 64 * (DD / 4); idx += 128) {
        int r = idx >> 5, c4 = idx & 31;
        float4 v = (node0 + r < n)
                 ? ((const float4*)(x + (size_t)(node0 + r) * DD))[c4]
                 : make_float4(0.f, 0.f, 0.f, 0.f);
        v.x = f2tf32f(v.x); v.y = f2tf32f(v.y);
        v.z = f2tf32f(v.z); v.w = f2tf32f(v.w);
        *(float4*)&xs[r][c4 * 4] = v;
    }
    __syncthreads();

    int warp = tid >> 5, lane = tid & 31;
    int g = lane >> 2, tig = lane & 3;
    int m0 = warp * 16;

    float acc[8][4];
#pragma unroll
    for (int nt = 0; nt < 8; nt++)
#pragma unroll
        for (int c = 0; c < 4; c++) acc[nt][c] = 0.0f;

#pragma unroll
    for (int kc = 0; kc < 16; kc++) {
        int k0 = kc * 8;
        unsigned a0 = __float_as_uint(xs[m0 + g][k0 + tig]);
        unsigned a1 = __float_as_uint(xs[m0 + g + 8][k0 + tig]);
        unsigned a2 = __float_as_uint(xs[m0 + g][k0 + tig + 4]);
        unsigned a3 = __float_as_uint(xs[m0 + g + 8][k0 + tig + 4]);

#pragma unroll
        for (int nt = 0; nt < 8; nt++) {
            unsigned b0 = __float_as_uint(wt[k0 + tig][nt * 8 + g]);
            unsigned b1 = __float_as_uint(wt[k0 + tig + 4][nt * 8 + g]);
            mma_tf32(acc[nt], a0, a1, a2, a3, b0, b1);
        }
    }

    int node_a = node0 + m0 + g;
    int node_b = node_a + 8;
#pragma unroll
    for (int nt = 0; nt < 8; nt++) {
        int j = nt * 8 + 2 * tig;
        float* base = (j < HH) ? g_y1 : g_z1;
        int jj = j & 31;
        if (node_a < n) *(float2*)&base[node_a * HH + jj] = make_float2(acc[nt][0], acc[nt][1]);
        if (node_b < n) *(float2*)&base[node_b * HH + jj] = make_float2(acc[nt][2], acc[nt][3]);
    }
}

// -------- layer-1 edge scatter: cooperative 8-edges-per-8-lane-group --------
__global__ __launch_bounds__(256) void scatter1_kernel(const void* __restrict__ ei, long long E) {
    long long t = (long long)blockIdx.x * blockDim.x + threadIdx.x;
    long long base = (t >> 3) * 8;       // first edge of this group
    int sub = (int)(t & 7);              // this lane's feature chunk
    int is64 = g_is64;

    long long my_e = base + sub;
    int my_src = 0, my_dst = 0;
    bool my_valid = (my_e < E);
    if (my_valid) {
        my_src = edge_at32(ei, my_e, is64);
        my_dst = edge_at32(ei, E + my_e, is64);
    }
    int lane = threadIdx.x & 31;
    int gbase = lane & ~7;               // leader lane of this 8-group

#pragma unroll
    for (int i = 0; i < 8; i++) {
        int s = __shfl_sync(0xFFFFFFFFu, my_src, gbase + i);
        int d = __shfl_sync(0xFFFFFFFFu, my_dst, gbase + i);
        if (base + i < E) {
            float4 v = *(const float4*)&g_y1[s * HH + sub * 4];
            atomicAdd((float4*)&g_agg[d * HH + sub * 4], v);
        }
    }
    if (my_valid) atomicAdd(&g_deg[my_dst], 1.0f);
}

// -------- layer-1 epilogue + layer-2 linear: 8 threads/node --------
// Global loads issued BEFORE the smem staging barrier to overlap latency.
__global__ __launch_bounds__(256) void epi_kernel(
    const float* __restrict__ b1,
    const float* __restrict__ W2l,
    const float* __restrict__ W2r,
    int n)
{
    __shared__ float sb1[HH], swl[HH], swr[HH];
    int t = blockIdx.x * blockDim.x + threadIdx.x;
    int node = t >> 3;         // 8 threads per node
    int q = t & 7;             // 4-feature slice
    bool valid = (node < n);
    int nd = valid ? node : (n - 1);   // clamp (keep full warp for shfl)

    // issue global loads first (independent of smem weights)
    float4 a = *(const float4*)&g_agg[(size_t)nd * HH + q * 4];
    float4 z = *(const float4*)&g_z1[(size_t)nd * HH + q * 4];
    float dg = g_deg[nd];

    if (threadIdx.x < HH) {
        sb1[threadIdx.x] = b1[threadIdx.x];
        swl[threadIdx.x] = W2l[threadIdx.x];
        swr[threadIdx.x] = W2r[threadIdx.x];
    }
    __syncthreads();

    float rdeg = 1.0f / fmaxf(dg, 1.0f);
    int k = q * 4;
    float h0 = fmaxf(fmaf(a.x, rdeg, sb1[k + 0] + z.x), 0.0f);
    float h1 = fmaxf(fmaf(a.y, rdeg, sb1[k + 1] + z.y), 0.0f);
    float h2 = fmaxf(fmaf(a.z, rdeg, sb1[k + 2] + z.z), 0.0f);
    float h3 = fmaxf(fmaf(a.w, rdeg, sb1[k + 3] + z.w), 0.0f);
    float sl = h0 * swl[k + 0] + h1 * swl[k + 1] + h2 * swl[k + 2] + h3 * swl[k + 3];
    float sr = h0 * swr[k + 0] + h1 * swr[k + 1] + h2 * swr[k + 2] + h3 * swr[k + 3];
    sl += __shfl_xor_sync(0xFFFFFFFFu, sl, 1);
    sr += __shfl_xor_sync(0xFFFFFFFFu, sr, 1);
    sl += __shfl_xor_sync(0xFFFFFFFFu, sl, 2);
    sr += __shfl_xor_sync(0xFFFFFFFFu, sr, 2);
    sl += __shfl_xor_sync(0xFFFFFFFFu, sl, 4);
    sr += __shfl_xor_sync(0xFFFFFFFFu, sr, 4);
    if (valid && q == 0) { g_sl[node] = sl; g_sr[node] = sr; }
}

// -------- layer-2 edge scatter: 1 edge/thread (max warps, min front-batch) ---
__global__ __launch_bounds__(256) void scatter2_kernel(const void* __restrict__ ei, long long E) {
    long long e = (long long)blockIdx.x * blockDim.x + threadIdx.x;
    if (e >= E) return;
    int is64 = g_is64;
    int s = edge_at32(ei, e, is64);
    int d = edge_at32(ei, E + e, is64);
    atomicAdd(&g_agg2[d], g_sl[s]);
}

// -------- final: sigmoid(agg2/deg + b2 + s_r) --------
__global__ __launch_bounds__(256) void final_kernel(const float* __restrict__ b2,
                                                    float* __restrict__ out, int n) {
    int i = blockIdx.x * blockDim.x + threadIdx.x;
    if (i >= n) return;
    float rdeg = 1.0f / fmaxf(g_deg[i], 1.0f);
    float v = fmaf(g_agg2[i], rdeg, b2[0] + g_sr[i]);
    out[i] = 1.0f / (1.0f + expf(-v));
}

extern "C" void kernel_launch(void* const* d_in, const int* in_sizes, int n_in,
                              void* d_out, int out_size) {
    const float* x   = (const float*)d_in[0];
    const void*  ei  = d_in[1];
    const float* W1l = (const float*)d_in[2];
    const float* b1  = (const float*)d_in[3];
    const float* W1r = (const float*)d_in[4];
    const float* W2l = (const float*)d_in[5];
    const float* b2  = (const float*)d_in[6];
    const float* W2r = (const float*)d_in[7];
    float* out = (float*)d_out;

    int n = in_sizes[0] / DD;            // 50000
    long long E = in_sizes[1] / 2;       // 800000

    cudaFuncSetAttribute(lin1_mma_kernel,
                         cudaFuncAttributeMaxDynamicSharedMemorySize,
                         LIN1_SMEM_BYTES);

    lin1_mma_kernel<<<(n + 63) / 64, 128, LIN1_SMEM_BYTES>>>(
        x, W1l, W1r, (const unsigned*)ei, n);
    {
        long long threads = ((E + 7) >> 3) << 3;   // one thread per edge, groups of 8
        scatter1_kernel<<<(unsigned)((threads + 255) / 256), 256>>>(ei, E);
    }
    epi_kernel<<<(n * 8 + 255) / 256, 256>>>(b1, W2l, W2r, n);
    scatter2_kernel<<<(unsigned)((E + 255) / 256), 256>>>(ei, E);
    final_kernel<<<(n + 255) / 256, 256>>>(b2, out, n);
}

// round 15
// speedup vs baseline: 1.5545x; 1.0961x over previous
#include <cuda_runtime.h>
#include <cuda_bf16.h>
#include <cuda_fp16.h>

// Problem constants (fixed shapes for this problem)
#define NN 50000
#define EE 800000
#define DD 128
#define HH 32

// -------- scratch (no allocations allowed) --------
__device__ __align__(16) __half2 g_y1h[NN * 16]; // x @ W1_l^T packed fp16x2
__device__ __align__(16) float  g_z1[NN * HH];   // x @ W1_r^T (fp32)
__device__ __align__(16) __half2 g_aggh[NN * 16];// scatter-sum of y1 (fp16x2)
__device__ __align__(16) float  g_deg[NN];
__device__ __align__(16) float  g_sl[NN];        // h @ W2_l^T
__device__ __align__(16) float  g_sr[NN];        // h @ W2_r^T
__device__ __align__(16) float  g_agg2[NN];      // scatter-sum of s_l
__device__ int   g_is64;                         // edge_index dtype flag

// load node index (always < 2^31) as 32-bit regardless of storage width
__device__ __forceinline__ int edge_at32(const void* ei, long long pos, int is64) {
    return is64 ? ((const int*)ei)[2 * pos] : ((const int*)ei)[pos];
}

// -------- tf32 helpers --------
__device__ __forceinline__ float f2tf32f(float f) {
    unsigned u;
    asm("cvt.rna.tf32.f32 %0, %1;" : "=r"(u) : "f"(f));
    return __uint_as_float(u);
}
__device__ __forceinline__ void mma_tf32(float* d, unsigned a0, unsigned a1,
                                         unsigned a2, unsigned a3,
                                         unsigned b0, unsigned b1) {
    asm volatile(
        "mma.sync.aligned.m16n8k8.row.col.f32.tf32.tf32.f32 "
        "{%0,%1,%2,%3}, {%4,%5,%6,%7}, {%8,%9}, {%0,%1,%2,%3};\n"
        : "+f"(d[0]), "+f"(d[1]), "+f"(d[2]), "+f"(d[3])
        : "r"(a0), "r"(a1), "r"(a2), "r"(a3), "r"(b0), "r"(b1));
}

// Dynamic smem layout: xs[64][132] then wt[128][72]
#define XS_STRIDE 132
#define WT_STRIDE 72
#define XS_ELEMS  (64 * XS_STRIDE)
#define WT_ELEMS  (128 * WT_STRIDE)
#define LIN1_SMEM_BYTES ((XS_ELEMS + WT_ELEMS) * (int)sizeof(float))

// -------- fused: init (zero accumulators, dtype detect) + tf32 MMA linear ----
__global__ __launch_bounds__(128) void lin1_mma_kernel(
    const float* __restrict__ x,
    const float* __restrict__ W1l,
    const float* __restrict__ W1r,
    const unsigned* __restrict__ ei_words,
    int n)
{
    extern __shared__ float smem[];
    float (*xs)[XS_STRIDE] = (float (*)[XS_STRIDE])smem;              // 64 x 132
    float (*wt)[WT_STRIDE] = (float (*)[WT_STRIDE])(smem + XS_ELEMS); // 128 x 72

    int tid = threadIdx.x;
    int node0 = blockIdx.x * 64;

    // ---- folded init duties ----
    if (blockIdx.x == 0) {
        __shared__ int flag;
        if (tid == 0) flag = 1;
        __syncthreads();
        unsigned w = ei_words[2 * tid + 1];  // high words if int64
        if (w != 0u) flag = 0;
        __syncthreads();
        if (tid == 0) g_is64 = flag;
    }
    {
        uint4 z4u = make_uint4(0u, 0u, 0u, 0u);
        int lim = n - node0; if (lim > 64) lim = 64;
        // agg rows: 64B/node = 4 uint4 per node
        uint4* aggp = (uint4*)&g_aggh[(size_t)node0 * 16];
        for (int i = tid; i < lim * 4; i += 128) aggp[i] = z4u;
        for (int i = tid; i < lim; i += 128) {
            g_deg[node0 + i] = 0.0f;
            g_agg2[node0 + i] = 0.0f;
        }
    }

    // ---- weight + x tiles (rounded to tf32 in smem) ----
    for (int idx = tid; idx < DD * 64; idx += 128) {
        int k = idx & 127, j = idx >> 7;
        float w = (j < HH) ? W1l[j * DD + k] : W1r[(j - HH) * DD + k];
        wt[k][j] = f2tf32f(w);
    }
    for (int idx = tid; idx < 64 * (DD / 4); idx += 128) {
        int r = idx >> 5, c4 = idx & 31;
        float4 v = (node0 + r < n)
                 ? ((const float4*)(x + (size_t)(node0 + r) * DD))[c4]
                 : make_float4(0.f, 0.f, 0.f, 0.f);
        v.x = f2tf32f(v.x); v.y = f2tf32f(v.y);
        v.z = f2tf32f(v.z); v.w = f2tf32f(v.w);
        *(float4*)&xs[r][c4 * 4] = v;
    }
    __syncthreads();

    int warp = tid >> 5, lane = tid & 31;
    int g = lane >> 2, tig = lane & 3;
    int m0 = warp * 16;

    float acc[8][4];
#pragma unroll
    for (int nt = 0; nt < 8; nt++)
#pragma unroll
        for (int c = 0; c < 4; c++) acc[nt][c] = 0.0f;

#pragma unroll
    for (int kc = 0; kc < 16; kc++) {
        int k0 = kc * 8;
        unsigned a0 = __float_as_uint(xs[m0 + g][k0 + tig]);
        unsigned a1 = __float_as_uint(xs[m0 + g + 8][k0 + tig]);
        unsigned a2 = __float_as_uint(xs[m0 + g][k0 + tig + 4]);
        unsigned a3 = __float_as_uint(xs[m0 + g + 8][k0 + tig + 4]);

#pragma unroll
        for (int nt = 0; nt < 8; nt++) {
            unsigned b0 = __float_as_uint(wt[k0 + tig][nt * 8 + g]);
            unsigned b1 = __float_as_uint(wt[k0 + tig + 4][nt * 8 + g]);
            mma_tf32(acc[nt], a0, a1, a2, a3, b0, b1);
        }
    }

    int node_a = node0 + m0 + g;
    int node_b = node_a + 8;
#pragma unroll
    for (int nt = 0; nt < 8; nt++) {
        int j = nt * 8 + 2 * tig;       // even output column
        if (j < HH) {
            // y1 -> packed half2
            if (node_a < n) g_y1h[node_a * 16 + (j >> 1)] = __floats2half2_rn(acc[nt][0], acc[nt][1]);
            if (node_b < n) g_y1h[node_b * 16 + (j >> 1)] = __floats2half2_rn(acc[nt][2], acc[nt][3]);
        } else {
            int jj = j & 31;
            if (node_a < n) *(float2*)&g_z1[node_a * HH + jj] = make_float2(acc[nt][0], acc[nt][1]);
            if (node_b < n) *(float2*)&g_z1[node_b * HH + jj] = make_float2(acc[nt][2], acc[nt][3]);
        }
    }
}

// -------- layer-1 edge scatter: 4 lanes/edge, 16B vector fp16 REDs ----------
// Each lane covers 8 features via one red.global.add.noftz.v4.f16x2 (16B).
// Total RED lane-ops: E*4 = 3.2M (half of the f32x4 formulation).
__global__ __launch_bounds__(256) void scatter1_kernel(const void* __restrict__ ei, long long E) {
    long long t = (long long)blockIdx.x * blockDim.x + threadIdx.x;
    long long e = t >> 2;
    int sub = (int)(t & 3);              // 8-feature chunk (16B)
    if (e >= E) return;
    int is64 = g_is64;
    int s = edge_at32(ei, e, is64);
    int d = edge_at32(ei, E + e, is64);
    uint4 v = *(const uint4*)&g_y1h[(size_t)s * 16 + sub * 4];
    __half2* dstp = &g_aggh[(size_t)d * 16 + sub * 4];
    asm volatile(
        "red.global.add.noftz.v4.f16x2 [%0], {%1, %2, %3, %4};"
        :: "l"(dstp), "r"(v.x), "r"(v.y), "r"(v.z), "r"(v.w)
        : "memory");
    if (sub == 0) atomicAdd(&g_deg[d], 1.0f);
}

// -------- layer-1 epilogue + layer-2 linear: 8 threads/node ------------------
// Global loads issued BEFORE the smem staging barrier to overlap latency.
__global__ __launch_bounds__(256) void epi_kernel(
    const float* __restrict__ b1,
    const float* __restrict__ W2l,
    const float* __restrict__ W2r,
    int n)
{
    __shared__ float sb1[HH], swl[HH], swr[HH];
    int t = blockIdx.x * blockDim.x + threadIdx.x;
    int node = t >> 3;         // 8 threads per node
    int q = t & 7;             // 4-feature slice (2 half2)
    bool valid = (node < n);
    int nd = valid ? node : (n - 1);   // clamp (keep full warp for shfl)

    // issue global loads first (independent of smem weights)
    uint2 av = *(const uint2*)&g_aggh[(size_t)nd * 16 + q * 2];
    float4 z = *(const float4*)&g_z1[(size_t)nd * HH + q * 4];
    float dg = g_deg[nd];

    if (threadIdx.x < HH) {
        sb1[threadIdx.x] = b1[threadIdx.x];
        swl[threadIdx.x] = W2l[threadIdx.x];
        swr[threadIdx.x] = W2r[threadIdx.x];
    }
    __syncthreads();

    float2 a01 = __half22float2(*(__half2*)&av.x);
    float2 a23 = __half22float2(*(__half2*)&av.y);
    float rdeg = 1.0f / fmaxf(dg, 1.0f);
    int k = q * 4;
    float h0 = fmaxf(fmaf(a01.x, rdeg, sb1[k + 0] + z.x), 0.0f);
    float h1 = fmaxf(fmaf(a01.y, rdeg, sb1[k + 1] + z.y), 0.0f);
    float h2 = fmaxf(fmaf(a23.x, rdeg, sb1[k + 2] + z.z), 0.0f);
    float h3 = fmaxf(fmaf(a23.y, rdeg, sb1[k + 3] + z.w), 0.0f);
    float sl = h0 * swl[k + 0] + h1 * swl[k + 1] + h2 * swl[k + 2] + h3 * swl[k + 3];
    float sr = h0 * swr[k + 0] + h1 * swr[k + 1] + h2 * swr[k + 2] + h3 * swr[k + 3];
    sl += __shfl_xor_sync(0xFFFFFFFFu, sl, 1);
    sr += __shfl_xor_sync(0xFFFFFFFFu, sr, 1);
    sl += __shfl_xor_sync(0xFFFFFFFFu, sl, 2);
    sr += __shfl_xor_sync(0xFFFFFFFFu, sr, 2);
    sl += __shfl_xor_sync(0xFFFFFFFFu, sl, 4);
    sr += __shfl_xor_sync(0xFFFFFFFFu, sr, 4);
    if (valid && q == 0) { g_sl[node] = sl; g_sr[node] = sr; }
}

// -------- layer-2 edge scatter: 1 edge/thread --------------------------------
__global__ __launch_bounds__(256) void scatter2_kernel(const void* __restrict__ ei, long long E) {
    long long e = (long long)blockIdx.x * blockDim.x + threadIdx.x;
    if (e >= E) return;
    int is64 = g_is64;
    int s = edge_at32(ei, e, is64);
    int d = edge_at32(ei, E + e, is64);
    atomicAdd(&g_agg2[d], g_sl[s]);
}

// -------- final: sigmoid(agg2/deg + b2 + s_r) --------
__global__ __launch_bounds__(256) void final_kernel(const float* __restrict__ b2,
                                                    float* __restrict__ out, int n) {
    int i = blockIdx.x * blockDim.x + threadIdx.x;
    if (i >= n) return;
    float rdeg = 1.0f / fmaxf(g_deg[i], 1.0f);
    float v = fmaf(g_agg2[i], rdeg, b2[0] + g_sr[i]);
    out[i] = 1.0f / (1.0f + expf(-v));
}

extern "C" void kernel_launch(void* const* d_in, const int* in_sizes, int n_in,
                              void* d_out, int out_size) {
    const float* x   = (const float*)d_in[0];
    const void*  ei  = d_in[1];
    const float* W1l = (const float*)d_in[2];
    const float* b1  = (const float*)d_in[3];
    const float* W1r = (const float*)d_in[4];
    const float* W2l = (const float*)d_in[5];
    const float* b2  = (const float*)d_in[6];
    const float* W2r = (const float*)d_in[7];
    float* out = (float*)d_out;

    int n = in_sizes[0] / DD;            // 50000
    long long E = in_sizes[1] / 2;       // 800000

    cudaFuncSetAttribute(lin1_mma_kernel,
                         cudaFuncAttributeMaxDynamicSharedMemorySize,
                         LIN1_SMEM_BYTES);

    lin1_mma_kernel<<<(n + 63) / 64, 128, LIN1_SMEM_BYTES>>>(
        x, W1l, W1r, (const unsigned*)ei, n);
    {
        long long threads = E * 4;       // 4 lanes per edge
        scatter1_kernel<<<(unsigned)((threads + 255) / 256), 256>>>(ei, E);
    }
    epi_kernel<<<(n * 8 + 255) / 256, 256>>>(b1, W2l, W2r, n);
    scatter2_kernel<<<(unsigned)((E + 255) / 256), 256>>>(ei, E);
    final_kernel<<<(n + 255) / 256, 256>>>(b2, out, n);
}